// round 3
// baseline (speedup 1.0000x reference)
#include <cuda_runtime.h>
#include <math.h>

// BinEmbedding: out[p] = emb_table[tok(x[p])]
//   tok = 0 if isnan(x), else clamp(count(bins <= x) - 1, 0) + 1
//
// x (16*65536,) f32, bins (256,) f32, emb_table (257*64,) f32,
// out (B*L, 64) f32 = 268 MB written. HBM-write-bound target.
//
// R3: no bounds checks (grid tiles exactly), float4 x loads with 4
// interleaved searches/thread, copy phase in explicit batches of 8
// independent LDG.128 -> STG.128 pairs for MLP~8.

#define NUM_BINS 256
#define F4_PER_ROW 16              // H/4 = 64/4
#define THREADS 256
#define PPB 1024                   // positions per block; n_pos % PPB == 0
#define COPY_ITERS (PPB * F4_PER_ROW / THREADS)   // 64
#define BATCH 8

__device__ __forceinline__ int bin_token(float v, const float* sbins) {
    if (isnan(v)) return 0;
    int c = 0;
    #pragma unroll
    for (int s = NUM_BINS >> 1; s > 0; s >>= 1) {
        if (sbins[c + s - 1] <= v) c += s;
    }
    int idx = c - 1;
    return (idx < 0 ? 0 : idx) + 1;
}

__global__ __launch_bounds__(THREADS) void bin_embed_kernel(
    const float4* __restrict__ x4,     // n_pos/4 float4
    const float*  __restrict__ bins,
    const float4* __restrict__ emb4,   // (NUM_BINS+1) * 16 float4
    float4*       __restrict__ out)    // n_pos * 16 float4
{
    __shared__ float sbins[NUM_BINS];
    __shared__ int   stok[PPB];

    const int tid  = threadIdx.x;
    const int base = blockIdx.x * PPB;

    sbins[tid] = bins[tid];            // THREADS == NUM_BINS
    __syncthreads();

    // ---- Phase 1: 4 positions per thread, interleaved searches ----
    {
        float4 v = __ldg(&x4[(base >> 2) + tid]);
        int t0 = bin_token(v.x, sbins);
        int t1 = bin_token(v.y, sbins);
        int t2 = bin_token(v.z, sbins);
        int t3 = bin_token(v.w, sbins);
        stok[4 * tid + 0] = t0;
        stok[4 * tid + 1] = t1;
        stok[4 * tid + 2] = t2;
        stok[4 * tid + 3] = t3;
    }
    __syncthreads();

    // ---- Phase 2: gather + coalesced streaming stores ----
    // float4 element index = tid + i*THREADS, i in [0,64).
    // sub = tid & 15 is loop-invariant; row = (tid>>4) + i*16.
    const int sub  = tid & 15;
    int row        = tid >> 4;                       // advances by 16/iter
    float4* outp   = out + (size_t)base * F4_PER_ROW + tid;

    #pragma unroll
    for (int b = 0; b < COPY_ITERS / BATCH; b++) {
        float4 val[BATCH];
        #pragma unroll
        for (int k = 0; k < BATCH; k++) {
            int tok = stok[row + k * 16];
            val[k] = __ldg(&emb4[tok * F4_PER_ROW + sub]);
        }
        #pragma unroll
        for (int k = 0; k < BATCH; k++) {
            __stcs(outp + (size_t)k * THREADS, val[k]);
        }
        row  += BATCH * 16;
        outp += (size_t)BATCH * THREADS;
    }
}

extern "C" void kernel_launch(void* const* d_in, const int* in_sizes, int n_in,
                              void* d_out, int out_size)
{
    const float4* x4   = (const float4*)d_in[0];
    const float*  bins = (const float*)d_in[1];
    const float4* emb4 = (const float4*)d_in[2];
    float4* out = (float4*)d_out;

    int n_pos  = in_sizes[0];                  // 1,048,576; divisible by PPB
    int blocks = n_pos / PPB;                  // 1024

    bin_embed_kernel<<<blocks, THREADS>>>(x4, bins, emb4, out);
}

// round 4
// speedup vs baseline: 1.0608x; 1.0608x over previous
#include <cuda_runtime.h>
#include <math.h>
#include <cstdint>

// BinEmbedding: out[p] = emb_table[tok(x[p])]
//   tok = 0 if isnan(x), else clamp(count(bins <= x) - 1, 0) + 1
//
// x (B*L,) f32, bins (256,) f32, emb_table (257*64,) f32,
// out (B*L, 64) f32 = 268 MB written.
//
// R4: stage each block's 64 KB output tile in smem (STS.128, cheap issue),
// then one cp.async.bulk smem->gmem per block so the TMA engine does the
// HBM writes instead of per-thread STG.128 (12 cyc issue each).

#define NUM_BINS 256
#define F4_PER_ROW 16                 // 64 floats / 4
#define THREADS 256
#define PPB 256                       // positions per block; tile = 64 KB
#define TILE_F4 (PPB * F4_PER_ROW)    // 4096 float4
#define TILE_BYTES (TILE_F4 * 16)     // 65536
#define COPY_ITERS (TILE_F4 / THREADS)  // 16
#define BATCH 8

__device__ __forceinline__ uint32_t smem_u32(const void* p) {
    return (uint32_t)__cvta_generic_to_shared(p);
}

__global__ __launch_bounds__(THREADS) void bin_embed_kernel(
    const float*  __restrict__ x,
    const float*  __restrict__ bins,
    const float4* __restrict__ emb4,   // (NUM_BINS+1) * 16 float4
    float4*       __restrict__ out)    // n_pos * 16 float4
{
    __shared__ float sbins[NUM_BINS];
    __shared__ int   stok[PPB];
    __shared__ __align__(128) float4 tile[TILE_F4];   // 64 KB

    const int tid  = threadIdx.x;
    const int base = blockIdx.x * PPB;

    sbins[tid] = bins[tid];            // THREADS == NUM_BINS
    __syncthreads();

    // ---- Phase 1: one search per thread ----
    {
        float v = __ldg(&x[base + tid]);
        int tok = 0;
        if (!isnan(v)) {
            int c = 0;
            #pragma unroll
            for (int s = NUM_BINS >> 1; s > 0; s >>= 1) {
                if (sbins[c + s - 1] <= v) c += s;
            }
            int idx = c - 1;
            tok = (idx < 0 ? 0 : idx) + 1;
        }
        stok[tid] = tok;
    }
    __syncthreads();

    // ---- Phase 2: gather rows into smem tile (coalesced, conflict-free) ----
    // float4 index = tid + i*THREADS; row = idx>>4; sub = tid & 15 invariant.
    {
        const int sub = tid & 15;
        int row = tid >> 4;                    // advances by 16 per iter
        #pragma unroll
        for (int b = 0; b < COPY_ITERS / BATCH; b++) {
            float4 val[BATCH];
            #pragma unroll
            for (int k = 0; k < BATCH; k++) {
                int tok = stok[row + k * 16];
                val[k] = __ldg(&emb4[tok * F4_PER_ROW + sub]);
            }
            #pragma unroll
            for (int k = 0; k < BATCH; k++) {
                tile[tid + (b * BATCH + k) * THREADS] = val[k];
            }
            row += BATCH * 16;
        }
    }
    __syncthreads();

    // ---- Phase 3: single bulk async store, TMA engine writes HBM ----
    if (tid == 0) {
        asm volatile("fence.proxy.async.shared::cta;" ::: "memory");
        uint32_t src = smem_u32(tile);
        void* dst = (void*)(out + (size_t)base * F4_PER_ROW);
        asm volatile(
            "cp.async.bulk.global.shared::cta.bulk_group [%0], [%1], %2;"
            :: "l"(dst), "r"(src), "n"(TILE_BYTES) : "memory");
        asm volatile("cp.async.bulk.commit_group;" ::: "memory");
        // Wait until TMA finished reading smem before the CTA can exit and
        // its smem gets recycled for the next resident block.
        asm volatile("cp.async.bulk.wait_group.read 0;" ::: "memory");
    }
}

extern "C" void kernel_launch(void* const* d_in, const int* in_sizes, int n_in,
                              void* d_out, int out_size)
{
    const float*  x    = (const float*)d_in[0];
    const float*  bins = (const float*)d_in[1];
    const float4* emb4 = (const float4*)d_in[2];
    float4* out = (float4*)d_out;

    int n_pos  = in_sizes[0];                  // 1,048,576; divisible by PPB
    int blocks = n_pos / PPB;                  // 4096

    bin_embed_kernel<<<blocks, THREADS>>>(x, bins, emb4, out);
}

// round 5
// speedup vs baseline: 1.1007x; 1.0376x over previous
#include <cuda_runtime.h>
#include <math.h>

// BinEmbedding: out[p] = emb_table[tok(x[p])]
//   tok = 0 if isnan(x), else clamp(count(bins <= x) - 1, 0) + 1
//
// x (B*L,) f32, bins (256,) f32, emb_table (257*64,) f32,
// out (B*L, 64) f32 = 268 MB written. Steady-state floor = DRAM write drain.
//
// R5 = R2 skeleton (PPB 512 / 256 thr / grid 2048, best so far) with:
//  - all bounds checks removed (n_pos % PPB == 0)
//  - copy phase in explicit 8-wide independent LDG.128 batches (MLP~8)
//  - 2 independent search chains per thread in phase 1 (ILP=2)

#define NUM_BINS 256
#define F4_PER_ROW 16                    // 64 floats / 4
#define THREADS 256
#define PPB 512                          // positions per block
#define COPY_ITERS (PPB * F4_PER_ROW / THREADS)   // 32
#define BATCH 8

__global__ __launch_bounds__(THREADS) void bin_embed_kernel(
    const float*  __restrict__ x,
    const float*  __restrict__ bins,
    const float4* __restrict__ emb4,     // (NUM_BINS+1) * 16 float4
    float4*       __restrict__ out)      // n_pos * 16 float4
{
    __shared__ float sbins[NUM_BINS];
    __shared__ int   stok[PPB];

    const int tid  = threadIdx.x;
    const int base = blockIdx.x * PPB;

    sbins[tid] = bins[tid];              // THREADS == NUM_BINS
    __syncthreads();

    // ---- Phase 1: two independent searches per thread (ILP=2) ----
    {
        float v0 = __ldg(&x[base + tid]);
        float v1 = __ldg(&x[base + tid + THREADS]);
        int c0 = 0, c1 = 0;
        bool n0 = isnan(v0), n1 = isnan(v1);
        #pragma unroll
        for (int s = NUM_BINS >> 1; s > 0; s >>= 1) {
            if (sbins[c0 + s - 1] <= v0) c0 += s;
            if (sbins[c1 + s - 1] <= v1) c1 += s;
        }
        int i0 = c0 - 1; if (i0 < 0) i0 = 0;
        int i1 = c1 - 1; if (i1 < 0) i1 = 0;
        stok[tid]           = n0 ? 0 : i0 + 1;
        stok[tid + THREADS] = n1 ? 0 : i1 + 1;
    }
    __syncthreads();

    // ---- Phase 2: gather + coalesced streaming stores, 8-wide batches ----
    // float4 element index = tid + i*THREADS; sub = tid & 15 invariant;
    // row advances by 16 per iteration.
    const int sub = tid & 15;
    int row       = tid >> 4;
    float4* outp  = out + (size_t)base * F4_PER_ROW + tid;

    #pragma unroll
    for (int b = 0; b < COPY_ITERS / BATCH; b++) {   // 4 batches
        int tok[BATCH];
        #pragma unroll
        for (int k = 0; k < BATCH; k++) tok[k] = stok[row + k * 16];

        float4 val[BATCH];
        #pragma unroll
        for (int k = 0; k < BATCH; k++)
            val[k] = __ldg(&emb4[tok[k] * F4_PER_ROW + sub]);

        #pragma unroll
        for (int k = 0; k < BATCH; k++)
            __stcs(outp + (size_t)k * THREADS, val[k]);

        row  += BATCH * 16;
        outp += (size_t)BATCH * THREADS;
    }
}

extern "C" void kernel_launch(void* const* d_in, const int* in_sizes, int n_in,
                              void* d_out, int out_size)
{
    const float*  x    = (const float*)d_in[0];
    const float*  bins = (const float*)d_in[1];
    const float4* emb4 = (const float4*)d_in[2];
    float4* out = (float4*)d_out;

    int n_pos  = in_sizes[0];            // 1,048,576; divisible by PPB
    int blocks = n_pos / PPB;            // 2048

    bin_embed_kernel<<<blocks, THREADS>>>(x, bins, emb4, out);
}